// round 15
// baseline (speedup 1.0000x reference)
#include <cuda_runtime.h>

// Problem constants (fixed by the reference: B=8, N=M=4096, C=3)
#define BATCH   8
#define NPTS    4096
#define THREADS 256
#define TI      16            // x-groups (lanes 0..15 of each half-warp)
#define TJ      16            // y-groups; each handles 4 consecutive j per iter
#define XPT     8             // x points per thread
#define XBLK    (TI * XPT)    // 128 x points per block
#define NBX     (NPTS / XBLK) // 32
#define JSPLIT  4
#define JTILE   (NPTS / JSPLIT)   // 1024 y per block
#define JSTEP   (TJ * 4)          // 64 j consumed per iteration

// Scratch (no device allocs)
__device__ float g_colmin[BATCH * NBX * NPTS];       // 4 MB  [b][bx][j]
__device__ float g_rowmin[BATCH * JSPLIT * NPTS];    // 512KB [b][jq][i]
__device__ float g_part2[128];

// Fused pass: each distance computed ONCE, feeds both reductions.
// Plain L1 form: d = (|x0-y0| + |x1-y1|) + |x2-y2|
//   -> 3 FADD (sub) + 2 FADD with |.| operand modifiers, ALL on fma pipe;
//      alu pipe only carries the min reductions.
__global__ __launch_bounds__(THREADS, 3)
void chamfer_fused_kernel(const float* __restrict__ x,
                          const float* __restrict__ y) {
    __shared__ float sv0[JTILE], sv1[JTILE], sv2[JTILE];  // negated y coords
    __shared__ float rm[TJ][XBLK + 1];                    // row-min scratch
    const unsigned FULL = 0xffffffffu;

    const int b  = blockIdx.y;
    const int bx = blockIdx.x;
    const int jq = blockIdx.z;
    const int j0 = jq * JTILE;
    const int tid = threadIdx.x;
    const int ti = tid & (TI - 1);
    const int tj = tid >> 4;

    // Register-resident coords for this thread's 8 x points
    const float* Xb = x + ((size_t)b * NPTS + bx * XBLK + ti * XPT) * 3;
    float x0[XPT], x1[XPT], x2[XPT], row[XPT];
    #pragma unroll
    for (int k = 0; k < XPT; k++) {
        x0[k] = Xb[3 * k];
        x1[k] = Xb[3 * k + 1];
        x2[k] = Xb[3 * k + 2];
        row[k] = 1e30f;
    }

    // Stage this block's y quarter, negated, SoA (sub becomes add)
    const float* Yb = y + ((size_t)b * NPTS + j0) * 3;
    for (int k = tid; k < JTILE; k += THREADS) {
        const float* p = Yb + (size_t)k * 3;
        sv0[k] = -p[0];
        sv1[k] = -p[1];
        sv2[k] = -p[2];
    }
    __syncthreads();

    float* colout = g_colmin + ((size_t)(b * NBX + bx)) * NPTS + j0;

    // 16 iterations; each thread handles 4 consecutive j via LDS.128
    for (int jj = 0; jj < JTILE / JSTEP; jj++) {
        const int jb = jj * JSTEP + tj * 4;
        // Warp touches 2 consecutive 16B lines -> conflict-free broadcast
        float4 v0 = *(const float4*)&sv0[jb];
        float4 v1 = *(const float4*)&sv1[jb];
        float4 v2 = *(const float4*)&sv2[jb];

        float cm[4];
        #pragma unroll
        for (int jc = 0; jc < 4; jc++) {
            float y0 = jc == 0 ? v0.x : jc == 1 ? v0.y : jc == 2 ? v0.z : v0.w;
            float y1 = jc == 0 ? v1.x : jc == 1 ? v1.y : jc == 2 ? v1.z : v1.w;
            float y2 = jc == 0 ? v2.x : jc == 1 ? v2.y : jc == 2 ? v2.z : v2.w;

            float d[XPT];
            #pragma unroll
            for (int k = 0; k < XPT; k++) {
                float s0 = x0[k] + y0;            // FADD
                float s1 = x1[k] + y1;            // FADD
                float s2 = x2[k] + y2;            // FADD
                d[k] = (fabsf(s0) + fabsf(s1)) + fabsf(s2);  // 2x FADD |.|,|.|
                row[k] = fminf(row[k], d[k]);     // FMNMX (alu)
            }
            // col-min over this thread's 8 x (explicit tree)
            float c01 = fminf(d[0], d[1]), c23 = fminf(d[2], d[3]);
            float c45 = fminf(d[4], d[5]), c67 = fminf(d[6], d[7]);
            float cmin = fminf(fminf(c01, c23), fminf(c45, c67));
            // min across the 16 ti-lanes (xor of bits 0-3 stays in half-warp)
            #pragma unroll
            for (int o = 1; o < TI; o <<= 1)
                cmin = fminf(cmin, __shfl_xor_sync(FULL, cmin, o));
            cm[jc] = cmin;
        }
        if (ti == 0)   // 2 lanes/warp write adjacent float4s -> coalesced 32B
            *(float4*)&colout[jb] = make_float4(cm[0], cm[1], cm[2], cm[3]);
    }

    // Row-min: combine across the 16 tj groups, write per-x (min over jq later)
    #pragma unroll
    for (int k = 0; k < XPT; k++)
        rm[tj][ti * XPT + k] = row[k];
    __syncthreads();

    if (tid < XBLK) {
        float m = rm[0][tid];
        #pragma unroll
        for (int t = 1; t < TJ; t++)
            m = fminf(m, rm[t][tid]);
        g_rowmin[((size_t)(b * JSPLIT + jq)) * NPTS + bx * XBLK + tid] = m;
    }
}

// Combine: per (b,i)  col-min over 32 x-blocks  +  row-min over 4 j-quarters,
// then per-block partial sums. Fixed order -> deterministic.
__global__ __launch_bounds__(256)
void combine_kernel() {
    __shared__ float warp_s[8];
    const int idx = blockIdx.x * 256 + threadIdx.x;     // 0..32767
    const int b = idx >> 12, i = idx & (NPTS - 1);

    const float* cbase = g_colmin + (size_t)b * NBX * NPTS + i;
    float cm = cbase[0];
    #pragma unroll
    for (int bx = 1; bx < NBX; bx++)
        cm = fminf(cm, cbase[(size_t)bx * NPTS]);

    const float* rbase = g_rowmin + (size_t)b * JSPLIT * NPTS + i;
    float rv = rbase[0];
    #pragma unroll
    for (int q = 1; q < JSPLIT; q++)
        rv = fminf(rv, rbase[(size_t)q * NPTS]);

    float s = cm + rv;
    #pragma unroll
    for (int o = 16; o > 0; o >>= 1)
        s += __shfl_down_sync(0xffffffffu, s, o);
    if ((threadIdx.x & 31) == 0) warp_s[threadIdx.x >> 5] = s;
    __syncthreads();
    if (threadIdx.x == 0) {
        float t = 0.0f;
        #pragma unroll
        for (int w = 0; w < 8; w++) t += warp_s[w];
        g_part2[blockIdx.x] = t;
    }
}

// total = (sum row-mins + sum col-mins) / (B*N)  ==  mean_x + mean_y  (N == M)
__global__ void final_reduce_kernel(float* __restrict__ out) {
    __shared__ float warp_s[4];
    const int tid = threadIdx.x;   // 128

    float s = g_part2[tid];
    #pragma unroll
    for (int o = 16; o > 0; o >>= 1)
        s += __shfl_down_sync(0xffffffffu, s, o);
    if ((tid & 31) == 0) warp_s[tid >> 5] = s;
    __syncthreads();
    if (tid == 0)
        out[0] = (warp_s[0] + warp_s[1] + warp_s[2] + warp_s[3])
                 * (1.0f / (float)(BATCH * NPTS));
}

extern "C" void kernel_launch(void* const* d_in, const int* in_sizes, int n_in,
                              void* d_out, int out_size) {
    const float* x = (const float*)d_in[0];
    const float* y = (const float*)d_in[1];
    float* out = (float*)d_out;
    (void)in_sizes; (void)n_in; (void)out_size;

    dim3 grid(NBX, BATCH, JSPLIT);         // 32 x 8 x 4 = 1024 blocks
    chamfer_fused_kernel<<<grid, THREADS>>>(x, y);
    combine_kernel<<<128, 256>>>();
    final_reduce_kernel<<<1, 128>>>(out);
}

// round 17
// speedup vs baseline: 1.3858x; 1.3858x over previous
#include <cuda_runtime.h>
#include <cuda_fp16.h>

// Problem constants (fixed by the reference: B=8, N=M=4096, C=3)
#define BATCH   8
#define NPTS    4096
#define THREADS 256
#define TI      16            // x-groups (lanes 0..15 of each half-warp)
#define TJ      16            // y-groups; each handles 8 consecutive j per iter
#define XPT     8             // x points per thread
#define XBLK    (TI * XPT)    // 128 x points per block
#define NBX     (NPTS / XBLK) // 32
#define JSPLIT  4
#define JTILE   (NPTS / JSPLIT)   // 1024 y per block
#define JSTEP   (TJ * 8)          // 128 j consumed per iteration

// Scratch (no device allocs)
__device__ __half g_colmin[BATCH * NBX * NPTS];      // 2 MB  [b][bx][j]
__device__ float  g_rowmin[BATCH * JSPLIT * NPTS];   // 512KB [b][jq][i]
__device__ float  g_part2[128];

// Fused pass in fp16x2: each distance computed ONCE (for a PAIR of j per
// register lane-pair), feeds both reductions.
//   d = |x0-y0| + |x1-y1| + |x2-y2|   (HADD2 + HABS2 + HMNMX2)
__global__ __launch_bounds__(THREADS, 3)
void chamfer_fused_kernel(const float* __restrict__ x,
                          const float* __restrict__ y) {
    __shared__ __half2 sv0[JTILE / 2], sv1[JTILE / 2], sv2[JTILE / 2];
    __shared__ float rm[TJ][XBLK + 1];                // row-min scratch
    const unsigned FULL = 0xffffffffu;

    const int b  = blockIdx.y;
    const int bx = blockIdx.x;
    const int jq = blockIdx.z;
    const int j0 = jq * JTILE;
    const int tid = threadIdx.x;
    const int ti = tid & (TI - 1);
    const int tj = tid >> 4;

    // Register-resident broadcast fp16 coords for this thread's 8 x points
    const float* Xb = x + ((size_t)b * NPTS + bx * XBLK + ti * XPT) * 3;
    __half2 xh0[XPT], xh1[XPT], xh2[XPT], row2[XPT];
    #pragma unroll
    for (int k = 0; k < XPT; k++) {
        xh0[k] = __float2half2_rn(Xb[3 * k]);
        xh1[k] = __float2half2_rn(Xb[3 * k + 1]);
        xh2[k] = __float2half2_rn(Xb[3 * k + 2]);
        row2[k] = __float2half2_rn(65000.0f);
    }

    // Stage this block's y quarter: NEGATED fp16 pairs (j even/odd), SoA
    const float* Yb = y + ((size_t)b * NPTS + j0) * 3;
    for (int k2 = tid; k2 < JTILE / 2; k2 += THREADS) {
        const float* p = Yb + (size_t)k2 * 6;
        sv0[k2] = __floats2half2_rn(-p[0], -p[3]);
        sv1[k2] = __floats2half2_rn(-p[1], -p[4]);
        sv2[k2] = __floats2half2_rn(-p[2], -p[5]);
    }
    __syncthreads();

    __half* colout = g_colmin + ((size_t)(b * NBX + bx)) * NPTS + j0;

    // 8 iterations; each thread handles 8 consecutive j (4 half2) via LDS.128
    for (int jj = 0; jj < JTILE / JSTEP; jj++) {
        const int hb = jj * (JSTEP / 2) * TJ / TJ * TJ ? 0 : 0; (void)hb;
        const int vidx = jj * TJ + tj;          // uint4 index into sv*
        // Warp touches 2 consecutive 16B lines -> conflict-free broadcast
        uint4 r0 = ((const uint4*)sv0)[vidx];
        uint4 r1 = ((const uint4*)sv1)[vidx];
        uint4 r2 = ((const uint4*)sv2)[vidx];
        const __half2* y0g = (const __half2*)&r0;
        const __half2* y1g = (const __half2*)&r1;
        const __half2* y2g = (const __half2*)&r2;

        __half2 cm[4];
        #pragma unroll
        for (int jc = 0; jc < 4; jc++) {
            __half2 ny0 = y0g[jc], ny1 = y1g[jc], ny2 = y2g[jc];

            __half2 d2[XPT];
            #pragma unroll
            for (int k = 0; k < XPT; k++) {
                __half2 s0 = __habs2(__hadd2(xh0[k], ny0));
                __half2 s1 = __habs2(__hadd2(xh1[k], ny1));
                __half2 s2 = __habs2(__hadd2(xh2[k], ny2));
                d2[k] = __hadd2(__hadd2(s0, s1), s2);
                row2[k] = __hmin2(row2[k], d2[k]);
            }
            // col-min tree over this thread's 8 x (2 j's per half2 lane)
            __half2 c01 = __hmin2(d2[0], d2[1]), c23 = __hmin2(d2[2], d2[3]);
            __half2 c45 = __hmin2(d2[4], d2[5]), c67 = __hmin2(d2[6], d2[7]);
            __half2 cmin = __hmin2(__hmin2(c01, c23), __hmin2(c45, c67));
            // min across the 16 ti-lanes (xor of bits 0-3 stays in half-warp)
            #pragma unroll
            for (int o = 1; o < TI; o <<= 1)
                cmin = __hmin2(cmin, __shfl_xor_sync(FULL, cmin, o));
            cm[jc] = cmin;
        }
        if (ti == 0) {   // 2 lanes/warp write adjacent 16B -> coalesced
            uint4 out;
            out.x = *(const unsigned*)&cm[0];
            out.y = *(const unsigned*)&cm[1];
            out.z = *(const unsigned*)&cm[2];
            out.w = *(const unsigned*)&cm[3];
            *(uint4*)&colout[jj * JSTEP + tj * 8] = out;
        }
    }

    // Row-min: fold the two half lanes, combine across 16 tj groups
    #pragma unroll
    for (int k = 0; k < XPT; k++)
        rm[tj][ti * XPT + k] = fminf(__low2float(row2[k]), __high2float(row2[k]));
    __syncthreads();

    if (tid < XBLK) {
        float m = rm[0][tid];
        #pragma unroll
        for (int t = 1; t < TJ; t++)
            m = fminf(m, rm[t][tid]);
        g_rowmin[((size_t)(b * JSPLIT + jq)) * NPTS + bx * XBLK + tid] = m;
    }
}

// Combine: per (b,i)  col-min over 32 x-blocks (fp16 -> fp32)  +  row-min over
// 4 j-quarters, then per-block partial sums. Fixed order -> deterministic.
__global__ __launch_bounds__(256)
void combine_kernel() {
    __shared__ float warp_s[8];
    const int idx = blockIdx.x * 256 + threadIdx.x;     // 0..32767
    const int b = idx >> 12, i = idx & (NPTS - 1);

    const __half* cbase = g_colmin + (size_t)b * NBX * NPTS + i;
    float cm = __half2float(cbase[0]);
    #pragma unroll
    for (int bx = 1; bx < NBX; bx++)
        cm = fminf(cm, __half2float(cbase[(size_t)bx * NPTS]));

    const float* rbase = g_rowmin + (size_t)b * JSPLIT * NPTS + i;
    float rv = rbase[0];
    #pragma unroll
    for (int q = 1; q < JSPLIT; q++)
        rv = fminf(rv, rbase[(size_t)q * NPTS]);

    float s = cm + rv;
    #pragma unroll
    for (int o = 16; o > 0; o >>= 1)
        s += __shfl_down_sync(0xffffffffu, s, o);
    if ((threadIdx.x & 31) == 0) warp_s[threadIdx.x >> 5] = s;
    __syncthreads();
    if (threadIdx.x == 0) {
        float t = 0.0f;
        #pragma unroll
        for (int w = 0; w < 8; w++) t += warp_s[w];
        g_part2[blockIdx.x] = t;
    }
}

// total = (sum row-mins + sum col-mins) / (B*N)  ==  mean_x + mean_y  (N == M)
__global__ void final_reduce_kernel(float* __restrict__ out) {
    __shared__ float warp_s[4];
    const int tid = threadIdx.x;   // 128

    float s = g_part2[tid];
    #pragma unroll
    for (int o = 16; o > 0; o >>= 1)
        s += __shfl_down_sync(0xffffffffu, s, o);
    if ((tid & 31) == 0) warp_s[tid >> 5] = s;
    __syncthreads();
    if (tid == 0)
        out[0] = (warp_s[0] + warp_s[1] + warp_s[2] + warp_s[3])
                 * (1.0f / (float)(BATCH * NPTS));
}

extern "C" void kernel_launch(void* const* d_in, const int* in_sizes, int n_in,
                              void* d_out, int out_size) {
    const float* x = (const float*)d_in[0];
    const float* y = (const float*)d_in[1];
    float* out = (float*)d_out;
    (void)in_sizes; (void)n_in; (void)out_size;

    dim3 grid(NBX, BATCH, JSPLIT);         // 32 x 8 x 4 = 1024 blocks
    chamfer_fused_kernel<<<grid, THREADS>>>(x, y);
    combine_kernel<<<128, 256>>>();
    final_reduce_kernel<<<1, 128>>>(out);
}